// round 8
// baseline (speedup 1.0000x reference)
#include <cuda_runtime.h>
#include <cuda_fp16.h>
#include <cuda_bf16.h>
#include <cstdint>

// Problem constants (DiffusionConv: N=50000, E=800000, C=64, K=3)
#define NMAX 50000
#define EMAX 800000
#define C    64

// -------- device scratch (no allocs allowed) --------
__device__ float g_T1[NMAX * C];
__device__ float g_T2[NMAX * C];
__device__ float g_T3[NMAX * C];
__device__ __align__(16) __half g_xh[NMAX * C];    // fp16 gather sources
__device__ __align__(16) __half g_T1h[NMAX * C];
__device__ __align__(16) __half g_T2h[NMAX * C];
__device__ float g_deg[NMAX];
__device__ float g_dinv[NMAX];
__device__ float g_W[4 * C * C];       // W0=Tf0, W1=Tb0+Tb1, W2=Tf1+Tb2, W3=Tf2

// CSR scratch
__device__ int   g_cnt[NMAX];
__device__ int   g_rowptr[NMAX + 1];
__device__ int   g_cur[NMAX];
__device__ int   g_bsum[128];
__device__ unsigned long long g_epack[EMAX];   // (norm<<32)|col, 8B per edge

// ---------------- packed fp32x2 helpers ----------------
#define FMA2(d, a, b) \
    asm("fma.rn.f32x2 %0, %1, %2, %3;" : "=l"(d) : "l"(a), "l"(b), "l"(d))

// ---------------- init: zero cnt/deg + convert x -> fp16 ----------------
__global__ void init_kernel(const float* __restrict__ x, int N) {
    int i = blockIdx.x * blockDim.x + threadIdx.x;
    if (i < N) { g_cnt[i] = 0; g_deg[i] = 0.f; }
    if (i < N * 8) {
        int row = i >> 3, ch = (i & 7) << 3;     // 8 channels per thread
        const float4* p = (const float4*)(x + (size_t)row * C + ch);
        float4 a = p[0], b = p[1];
        __half2 h0 = __floats2half2_rn(a.x, a.y);
        __half2 h1 = __floats2half2_rn(a.z, a.w);
        __half2 h2 = __floats2half2_rn(b.x, b.y);
        __half2 h3 = __floats2half2_rn(b.z, b.w);
        uint4 u;
        u.x = *(unsigned*)&h0; u.y = *(unsigned*)&h1;
        u.z = *(unsigned*)&h2; u.w = *(unsigned*)&h3;
        *(uint4*)(g_xh + (size_t)row * C + ch) = u;
    }
}

// ---------------- degree + histogram in one pass ----------------
__global__ void deg_hist_kernel(const int* __restrict__ row,
                                const float* __restrict__ w, int E) {
    int e = blockIdx.x * blockDim.x + threadIdx.x;
    if (e < E) {
        int r = row[e];
        atomicAdd(&g_deg[r], w[e]);
        atomicAdd(&g_cnt[r], 1);
    }
}

// ---------------- scan1: shuffle-based block scan of g_cnt (+dinv fused) ----
__global__ void scan1_kernel(int N) {
    __shared__ int wsum[16];
    int tid = threadIdx.x;
    int i = blockIdx.x * 512 + tid;
    int lane = tid & 31, wid = tid >> 5;

    int v = (i < N) ? g_cnt[i] : 0;
    int s = v;
#pragma unroll
    for (int off = 1; off < 32; off <<= 1) {
        int t = __shfl_up_sync(0xffffffffu, s, off);
        if (lane >= off) s += t;
    }
    if (lane == 31) wsum[wid] = s;
    __syncthreads();
    if (wid == 0) {
        int ws = (lane < 16) ? wsum[lane] : 0;
#pragma unroll
        for (int off = 1; off < 16; off <<= 1) {
            int t = __shfl_up_sync(0xffffffffu, ws, off);
            if (lane >= off) ws += t;
        }
        if (lane < 16) wsum[lane] = ws;
    }
    __syncthreads();
    int base = (wid > 0) ? wsum[wid - 1] : 0;
    if (i < N) g_rowptr[i] = base + s - v;       // block-local exclusive
    if (tid == 511) g_bsum[blockIdx.x] = base + s;

    // fused: dinv
    if (i < N) {
        float d = g_deg[i];
        g_dinv[i] = (d > 0.f) ? rsqrtf(d) : 0.f;
    }
}

__global__ void scan2_kernel(int nb) {           // single block, 128 threads
    int tid = threadIdx.x;
    int lane = tid & 31, wid = tid >> 5;
    __shared__ int wsum[4];
    int v = (tid < nb) ? g_bsum[tid] : 0;
    int s = v;
#pragma unroll
    for (int off = 1; off < 32; off <<= 1) {
        int t = __shfl_up_sync(0xffffffffu, s, off);
        if (lane >= off) s += t;
    }
    if (lane == 31) wsum[wid] = s;
    __syncthreads();
    if (tid == 0) {
        int a = wsum[0];
        int b = a + wsum[1];
        int c = b + wsum[2];
        wsum[1] = a; wsum[2] = b; wsum[3] = c; wsum[0] = 0;
    }
    __syncthreads();
    if (tid < nb) g_bsum[tid] = wsum[wid] + s - v;   // exclusive
}

__global__ void scan3_kernel(int N, int E) {
    int i = blockIdx.x * 512 + threadIdx.x;
    if (i < N) {
        int rp = g_rowptr[i] + g_bsum[blockIdx.x];
        g_rowptr[i] = rp;
        g_cur[i] = rp;
    }
    if (i == 0) g_rowptr[N] = E;
}

// ---------------- scatter edges into packed CSR (norm fused) ----------------
__global__ void scatter_kernel(const int* __restrict__ row,
                               const int* __restrict__ col,
                               const float* __restrict__ w, int E) {
    int e = blockIdx.x * blockDim.x + threadIdx.x;
    if (e < E) {
        int r = row[e], c = col[e];
        float nm = g_dinv[r] * w[e] * g_dinv[c];
        int pos = atomicAdd(&g_cur[r], 1);
        unsigned long long p =
            ((unsigned long long)__float_as_uint(nm) << 32) | (unsigned)c;
        g_epack[pos] = p;
    }
}

// ---------------- combine thetas ----------------
__global__ void wprep_kernel(const float* __restrict__ tf,
                             const float* __restrict__ tb) {
    int i = blockIdx.x * blockDim.x + threadIdx.x;
    if (i < C * C) {
        g_W[0 * C * C + i] = tf[0 * C * C + i];
        g_W[1 * C * C + i] = tb[0 * C * C + i] + tb[1 * C * C + i];
        g_W[2 * C * C + i] = tf[1 * C * C + i] + tb[2 * C * C + i];
        g_W[3 * C * C + i] = tf[2 * C * C + i];
    }
}

// ---------------- propagate via CSR gather: one warp per node ---------------
// fp16 gather sources (128B/row = 1 L1 wavefront/edge), fp32 accumulate.
// Writes fp32 dst (GEMM input) and fp16 dst (next pass's gather source).
__global__ void prop_csr_kernel(int step, int N) {
    const __half* __restrict__ src =
        (step == 0) ? g_xh : (step == 1 ? g_T1h : g_T2h);
    float* __restrict__ dst =
        (step == 0) ? g_T1 : (step == 1 ? g_T2 : g_T3);
    __half* __restrict__ dsth =
        (step == 0) ? g_T1h : (step == 1 ? g_T2h : ((__half*)0));

    int warp = (int)((blockIdx.x * blockDim.x + threadIdx.x) >> 5);
    if (warp >= N) return;
    int lane = threadIdx.x & 31;

    int beg = g_rowptr[warp];
    int end = g_rowptr[warp + 1];

    float ax = 0.f, ay = 0.f;
    int e = beg;
    for (; e + 4 <= end; e += 4) {
        unsigned long long p0 = g_epack[e + 0], p1 = g_epack[e + 1];
        unsigned long long p2 = g_epack[e + 2], p3 = g_epack[e + 3];
        int c0 = (int)(unsigned)p0, c1 = (int)(unsigned)p1;
        int c2 = (int)(unsigned)p2, c3 = (int)(unsigned)p3;
        float n0 = __uint_as_float((unsigned)(p0 >> 32));
        float n1 = __uint_as_float((unsigned)(p1 >> 32));
        float n2 = __uint_as_float((unsigned)(p2 >> 32));
        float n3 = __uint_as_float((unsigned)(p3 >> 32));
        float2 v0 = __half22float2(*(const __half2*)(src + ((size_t)c0 << 6) + (lane << 1)));
        float2 v1 = __half22float2(*(const __half2*)(src + ((size_t)c1 << 6) + (lane << 1)));
        float2 v2 = __half22float2(*(const __half2*)(src + ((size_t)c2 << 6) + (lane << 1)));
        float2 v3 = __half22float2(*(const __half2*)(src + ((size_t)c3 << 6) + (lane << 1)));
        ax = fmaf(n0, v0.x, ax); ay = fmaf(n0, v0.y, ay);
        ax = fmaf(n1, v1.x, ax); ay = fmaf(n1, v1.y, ay);
        ax = fmaf(n2, v2.x, ax); ay = fmaf(n2, v2.y, ay);
        ax = fmaf(n3, v3.x, ax); ay = fmaf(n3, v3.y, ay);
    }
    for (; e < end; e++) {
        unsigned long long p = g_epack[e];
        int c = (int)(unsigned)p;
        float nm = __uint_as_float((unsigned)(p >> 32));
        float2 v = __half22float2(*(const __half2*)(src + ((size_t)c << 6) + (lane << 1)));
        ax = fmaf(nm, v.x, ax); ay = fmaf(nm, v.y, ay);
    }
    *(float2*)(dst + ((size_t)warp << 6) + (lane << 1)) = make_float2(ax, ay);
    if (dsth)
        *(__half2*)(dsth + ((size_t)warp << 6) + (lane << 1)) =
            __floats2half2_rn(ax, ay);
}

// ---------------- fused epilogue GEMM: out = sum_s A_s @ W_s ----------------
// BM=128 rows/block, 256 threads. Thread tile: 8 rows x 4 cols, packed fp32x2.
#define BM 128
__global__ void out_gemm_kernel(const float* __restrict__ x,
                                float* __restrict__ out, int N) {
    __shared__ float sW[64 * 64];        // 16 KB
    __shared__ float sA[32 * 130];       // 16.25 KB, k-major

    int t = threadIdx.x;
    int tx = t & 15;                     // cols tx*4 .. tx*4+3
    int ty = t >> 4;                     // rows ty*8 .. ty*8+7
    int row0 = blockIdx.x * BM;
    int rbase = ty * 8;

    unsigned long long acc[4][4];
#pragma unroll
    for (int p = 0; p < 4; p++)
#pragma unroll
        for (int c = 0; c < 4; c++) acc[p][c] = 0ull;

#pragma unroll
    for (int s = 0; s < 4; s++) {
        const float* __restrict__ As =
            (s == 0) ? x : (s == 1 ? g_T1 : (s == 2 ? g_T2 : g_T3));

        __syncthreads();
        {
            const float4* Wg = (const float4*)(g_W + s * 64 * 64);
            float4* Ws4 = (float4*)sW;
            for (int i = t; i < 1024; i += 256) Ws4[i] = Wg[i];
        }

        for (int kh = 0; kh < 2; kh++) {
            __syncthreads();
#pragma unroll
            for (int it = 0; it < 4; it++) {
                int idx = it * 256 + t;
                int r = idx >> 3;
                int kc = (idx & 7) << 2;
                float4 v = make_float4(0.f, 0.f, 0.f, 0.f);
                int gr = row0 + r;
                if (gr < N)
                    v = *(const float4*)(As + (size_t)gr * 64 + kh * 32 + kc);
                sA[(kc + 0) * 130 + r] = v.x;
                sA[(kc + 1) * 130 + r] = v.y;
                sA[(kc + 2) * 130 + r] = v.z;
                sA[(kc + 3) * 130 + r] = v.w;
            }
            __syncthreads();
#pragma unroll
            for (int k4 = 0; k4 < 8; k4++) {
#pragma unroll
                for (int kk = 0; kk < 4; kk++) {
                    int kl = k4 * 4 + kk;
                    float4 w4 = *(const float4*)&sW[(kh * 32 + kl) * 64 + tx * 4];
                    unsigned long long wp0, wp1, wp2, wp3;
                    unsigned int u0 = __float_as_uint(w4.x);
                    unsigned int u1 = __float_as_uint(w4.y);
                    unsigned int u2 = __float_as_uint(w4.z);
                    unsigned int u3 = __float_as_uint(w4.w);
                    asm("mov.b64 %0,{%1,%1};" : "=l"(wp0) : "r"(u0));
                    asm("mov.b64 %0,{%1,%1};" : "=l"(wp1) : "r"(u1));
                    asm("mov.b64 %0,{%1,%1};" : "=l"(wp2) : "r"(u2));
                    asm("mov.b64 %0,{%1,%1};" : "=l"(wp3) : "r"(u3));
                    const unsigned long long* ap =
                        (const unsigned long long*)&sA[kl * 130 + rbase];
                    unsigned long long a0 = ap[0], a1 = ap[1];
                    unsigned long long a2 = ap[2], a3 = ap[3];
                    FMA2(acc[0][0], a0, wp0); FMA2(acc[0][1], a0, wp1);
                    FMA2(acc[0][2], a0, wp2); FMA2(acc[0][3], a0, wp3);
                    FMA2(acc[1][0], a1, wp0); FMA2(acc[1][1], a1, wp1);
                    FMA2(acc[1][2], a1, wp2); FMA2(acc[1][3], a1, wp3);
                    FMA2(acc[2][0], a2, wp0); FMA2(acc[2][1], a2, wp1);
                    FMA2(acc[2][2], a2, wp2); FMA2(acc[2][3], a2, wp3);
                    FMA2(acc[3][0], a3, wp0); FMA2(acc[3][1], a3, wp1);
                    FMA2(acc[3][2], a3, wp2); FMA2(acc[3][3], a3, wp3);
                }
            }
        }
    }

#pragma unroll
    for (int p = 0; p < 4; p++) {
        unsigned int lo[4], hi[4];
#pragma unroll
        for (int c = 0; c < 4; c++)
            asm("mov.b64 {%0,%1},%2;" : "=r"(lo[c]), "=r"(hi[c]) : "l"(acc[p][c]));
        int r_lo = row0 + rbase + 2 * p;
        if (r_lo < N) {
            float4 v = make_float4(__uint_as_float(lo[0]), __uint_as_float(lo[1]),
                                   __uint_as_float(lo[2]), __uint_as_float(lo[3]));
            *(float4*)(out + (size_t)r_lo * 64 + tx * 4) = v;
        }
        int r_hi = r_lo + 1;
        if (r_hi < N) {
            float4 v = make_float4(__uint_as_float(hi[0]), __uint_as_float(hi[1]),
                                   __uint_as_float(hi[2]), __uint_as_float(hi[3]));
            *(float4*)(out + (size_t)r_hi * 64 + tx * 4) = v;
        }
    }
}

// ============================================================================
extern "C" void kernel_launch(void* const* d_in, const int* in_sizes, int n_in,
                              void* d_out, int out_size) {
    const float* x  = (const float*)d_in[0];           // [N, 64]
    const int*   ei = (const int*)d_in[1];             // [2, E]
    const float* ew = (const float*)d_in[2];           // [E]
    const float* tf = (const float*)d_in[3];           // [3, 64, 64]
    const float* tb = (const float*)d_in[4];           // [3, 64, 64]
    float* out = (float*)d_out;

    const int N = in_sizes[0] / C;                     // 50000
    const int E = in_sizes[2];                         // 800000
    const int* row = ei;
    const int* col = ei + E;

    const int nb512 = (N + 511) / 512;                 // 98 scan blocks

    // 1. init (zero cnt/deg) + x -> fp16
    init_kernel<<<(N * 8 + 255) / 256, 256>>>(x, N);

    // 2. degree + histogram
    deg_hist_kernel<<<(E + 255) / 256, 256>>>(row, ew, E);

    // 3. scan (dinv fused into scan1) -> rowptr, cursors
    scan1_kernel<<<nb512, 512>>>(N);
    scan2_kernel<<<1, 128>>>(nb512);
    scan3_kernel<<<nb512, 512>>>(N, E);

    // 4. packed CSR scatter + weight fold
    scatter_kernel<<<(E + 255) / 256, 256>>>(row, col, ew, E);
    wprep_kernel<<<(C * C + 255) / 256, 256>>>(tf, tb);

    // 5. three diffusion steps (fp16 gather, fp32 accumulate)
    int prop_blocks = (N + 7) / 8;
    prop_csr_kernel<<<prop_blocks, 256>>>(0, N);
    prop_csr_kernel<<<prop_blocks, 256>>>(1, N);
    prop_csr_kernel<<<prop_blocks, 256>>>(2, N);

    // 6. fused 4-way GEMM epilogue (fp32x2 packed FMA)
    out_gemm_kernel<<<(N + BM - 1) / BM, 256>>>(x, out, N);
}

// round 9
// speedup vs baseline: 1.0577x; 1.0577x over previous
#include <cuda_runtime.h>
#include <cuda_bf16.h>
#include <cstdint>

// Problem constants (DiffusionConv: N=50000, E=800000, C=64, K=3)
#define NMAX 50000
#define EMAX 800000
#define C    64

// -------- device scratch (no allocs; statically zero-initialized) --------
__device__ float g_T1[NMAX * C];
__device__ float g_T2[NMAX * C];
__device__ float g_T3[NMAX * C];
__device__ float g_deg[NMAX];          // zeroed at end of scatter for next call
__device__ float g_dinv[NMAX];
__device__ int   g_cnt[NMAX];          // zeroed at end of scatter for next call
__device__ int   g_rowbeg[NMAX];
__device__ int   g_rowend[NMAX];
__device__ int   g_cur[NMAX];
__device__ int   g_total;              // segment-claim cursor, re-zeroed in scatter
__device__ unsigned long long g_epack[EMAX];   // (norm<<32)|col, 8B per edge

// ---------------- packed fp32x2 helpers ----------------
#define FMA2(d, a, b) \
    asm("fma.rn.f32x2 %0, %1, %2, %3;" : "=l"(d) : "l"(a), "l"(b), "l"(d))

// ---------------- degree + histogram (globals start zeroed) ----------------
__global__ void deg_hist_kernel(const int* __restrict__ row,
                                const float* __restrict__ w, int E) {
    int e = blockIdx.x * blockDim.x + threadIdx.x;
    if (e < E) {
        int r = row[e];
        atomicAdd(&g_deg[r], w[e]);
        atomicAdd(&g_cnt[r], 1);
    }
}

// ---------------- assign: unordered CSR segment claim + dinv ----------------
// Block-scan counts, claim a contiguous segment with ONE atomicAdd per block.
// Segments need not be in row order — CSR only requires per-row contiguity.
__global__ void assign_kernel(int N) {
    __shared__ int wsum[16];
    __shared__ int gbase;
    int tid = threadIdx.x;
    int i = blockIdx.x * 512 + tid;
    int lane = tid & 31, wid = tid >> 5;

    int v = (i < N) ? g_cnt[i] : 0;
    int s = v;
#pragma unroll
    for (int off = 1; off < 32; off <<= 1) {
        int t = __shfl_up_sync(0xffffffffu, s, off);
        if (lane >= off) s += t;
    }
    if (lane == 31) wsum[wid] = s;
    __syncthreads();
    if (wid == 0) {
        int ws = (lane < 16) ? wsum[lane] : 0;
#pragma unroll
        for (int off = 1; off < 16; off <<= 1) {
            int t = __shfl_up_sync(0xffffffffu, ws, off);
            if (lane >= off) ws += t;
        }
        if (lane < 16) wsum[lane] = ws;
    }
    __syncthreads();
    if (tid == 0) gbase = atomicAdd(&g_total, wsum[15]);   // claim block segment
    __syncthreads();
    if (i < N) {
        int base = gbase + ((wid > 0) ? wsum[wid - 1] : 0);
        int beg = base + s - v;
        g_rowbeg[i] = beg;
        g_rowend[i] = beg + v;
        g_cur[i] = beg;
        float d = g_deg[i];
        g_dinv[i] = (d > 0.f) ? rsqrtf(d) : 0.f;
    }
}

// ---------------- scatter edges into packed CSR (norm fused) ----------------
// Tail duty: re-zero cnt/deg/total so the NEXT call starts from clean state
// (call 1 is covered by static zero-init of __device__ globals).
__global__ void scatter_kernel(const int* __restrict__ row,
                               const int* __restrict__ col,
                               const float* __restrict__ w, int E, int N) {
    int e = blockIdx.x * blockDim.x + threadIdx.x;
    if (e < E) {
        int r = row[e], c = col[e];
        float nm = g_dinv[r] * w[e] * g_dinv[c];
        int pos = atomicAdd(&g_cur[r], 1);
        unsigned long long p =
            ((unsigned long long)__float_as_uint(nm) << 32) | (unsigned)c;
        g_epack[pos] = p;
    }
    if (e < N) { g_cnt[e] = 0; g_deg[e] = 0.f; }
    if (e == 0) g_total = 0;
}

// ---------------- propagate via CSR gather: one warp per node ---------------
// fp32 gather, fp32 accumulate, no atomics, unroll-8 for MLP.
// src/dst scratch selected device-side via step (never pass __device__ symbols
// from host — host shadow address != device address).
__global__ void prop_csr_kernel(const float* __restrict__ x_in, int step, int N) {
    const float* __restrict__ src =
        (step == 0) ? x_in : (step == 1 ? g_T1 : g_T2);
    float* __restrict__ dst =
        (step == 0) ? g_T1 : (step == 1 ? g_T2 : g_T3);

    int warp = (int)((blockIdx.x * blockDim.x + threadIdx.x) >> 5);
    if (warp >= N) return;
    int lane = threadIdx.x & 31;

    int beg = g_rowbeg[warp];
    int end = g_rowend[warp];

    float ax = 0.f, ay = 0.f;
    int e = beg;
    for (; e + 8 <= end; e += 8) {
        unsigned long long pk[8];
#pragma unroll
        for (int j = 0; j < 8; j++) pk[j] = g_epack[e + j];
        float2 v[8];
#pragma unroll
        for (int j = 0; j < 8; j++) {
            int c = (int)(unsigned)pk[j];
            v[j] = *(const float2*)(src + ((size_t)c << 6) + (lane << 1));
        }
#pragma unroll
        for (int j = 0; j < 8; j++) {
            float nm = __uint_as_float((unsigned)(pk[j] >> 32));
            ax = fmaf(nm, v[j].x, ax);
            ay = fmaf(nm, v[j].y, ay);
        }
    }
    for (; e < end; e++) {
        unsigned long long p = g_epack[e];
        int c = (int)(unsigned)p;
        float nm = __uint_as_float((unsigned)(p >> 32));
        float2 vv = *(const float2*)(src + ((size_t)c << 6) + (lane << 1));
        ax = fmaf(nm, vv.x, ax);
        ay = fmaf(nm, vv.y, ay);
    }
    *(float2*)(dst + ((size_t)warp << 6) + (lane << 1)) = make_float2(ax, ay);
}

// ---------------- fused epilogue GEMM: out = sum_s A_s @ W_s ----------------
// W_s folded from theta_forward/theta_backward during smem staging:
//   W0=Tf0, W1=Tb0+Tb1, W2=Tf1+Tb2, W3=Tf2
// BM=128 rows/block, 256 threads, thread tile 8 rows x 4 cols, packed fp32x2.
#define BM 128
__global__ void out_gemm_kernel(const float* __restrict__ x,
                                const float* __restrict__ tf,
                                const float* __restrict__ tb,
                                float* __restrict__ out, int N) {
    __shared__ float sW[64 * 64];        // 16 KB
    __shared__ float sA[32 * 130];       // 16.25 KB, k-major

    int t = threadIdx.x;
    int tx = t & 15;                     // cols tx*4 .. tx*4+3
    int ty = t >> 4;                     // rows ty*8 .. ty*8+7
    int row0 = blockIdx.x * BM;
    int rbase = ty * 8;

    unsigned long long acc[4][4];
#pragma unroll
    for (int p = 0; p < 4; p++)
#pragma unroll
        for (int c = 0; c < 4; c++) acc[p][c] = 0ull;

#pragma unroll
    for (int s = 0; s < 4; s++) {
        const float* __restrict__ As =
            (s == 0) ? x : (s == 1 ? g_T1 : (s == 2 ? g_T2 : g_T3));

        __syncthreads();   // prior iteration done reading sW/sA
        {   // stage W_s with theta fold (1024 float4s = 16 KB)
            const float4* tf4 = (const float4*)tf;   // [3][1024] float4
            const float4* tb4 = (const float4*)tb;
            float4* Ws4 = (float4*)sW;
            for (int i = t; i < 1024; i += 256) {
                float4 v;
                if (s == 0) v = tf4[i];
                else if (s == 1) {
                    float4 a = tb4[i], b = tb4[1024 + i];
                    v = make_float4(a.x + b.x, a.y + b.y, a.z + b.z, a.w + b.w);
                } else if (s == 2) {
                    float4 a = tf4[1024 + i], b = tb4[2048 + i];
                    v = make_float4(a.x + b.x, a.y + b.y, a.z + b.z, a.w + b.w);
                } else v = tf4[2048 + i];
                Ws4[i] = v;
            }
        }

        for (int kh = 0; kh < 2; kh++) {
            __syncthreads();
#pragma unroll
            for (int it = 0; it < 4; it++) {
                int idx = it * 256 + t;
                int r = idx >> 3;
                int kc = (idx & 7) << 2;
                float4 v = make_float4(0.f, 0.f, 0.f, 0.f);
                int gr = row0 + r;
                if (gr < N)
                    v = *(const float4*)(As + (size_t)gr * 64 + kh * 32 + kc);
                sA[(kc + 0) * 130 + r] = v.x;
                sA[(kc + 1) * 130 + r] = v.y;
                sA[(kc + 2) * 130 + r] = v.z;
                sA[(kc + 3) * 130 + r] = v.w;
            }
            __syncthreads();
#pragma unroll
            for (int k4 = 0; k4 < 8; k4++) {
#pragma unroll
                for (int kk = 0; kk < 4; kk++) {
                    int kl = k4 * 4 + kk;
                    float4 w4 = *(const float4*)&sW[(kh * 32 + kl) * 64 + tx * 4];
                    unsigned long long wp0, wp1, wp2, wp3;
                    unsigned int u0 = __float_as_uint(w4.x);
                    unsigned int u1 = __float_as_uint(w4.y);
                    unsigned int u2 = __float_as_uint(w4.z);
                    unsigned int u3 = __float_as_uint(w4.w);
                    asm("mov.b64 %0,{%1,%1};" : "=l"(wp0) : "r"(u0));
                    asm("mov.b64 %0,{%1,%1};" : "=l"(wp1) : "r"(u1));
                    asm("mov.b64 %0,{%1,%1};" : "=l"(wp2) : "r"(u2));
                    asm("mov.b64 %0,{%1,%1};" : "=l"(wp3) : "r"(u3));
                    const unsigned long long* ap =
                        (const unsigned long long*)&sA[kl * 130 + rbase];
                    unsigned long long a0 = ap[0], a1 = ap[1];
                    unsigned long long a2 = ap[2], a3 = ap[3];
                    FMA2(acc[0][0], a0, wp0); FMA2(acc[0][1], a0, wp1);
                    FMA2(acc[0][2], a0, wp2); FMA2(acc[0][3], a0, wp3);
                    FMA2(acc[1][0], a1, wp0); FMA2(acc[1][1], a1, wp1);
                    FMA2(acc[1][2], a1, wp2); FMA2(acc[1][3], a1, wp3);
                    FMA2(acc[2][0], a2, wp0); FMA2(acc[2][1], a2, wp1);
                    FMA2(acc[2][2], a2, wp2); FMA2(acc[2][3], a2, wp3);
                    FMA2(acc[3][0], a3, wp0); FMA2(acc[3][1], a3, wp1);
                    FMA2(acc[3][2], a3, wp2); FMA2(acc[3][3], a3, wp3);
                }
            }
        }
    }

#pragma unroll
    for (int p = 0; p < 4; p++) {
        unsigned int lo[4], hi[4];
#pragma unroll
        for (int c = 0; c < 4; c++)
            asm("mov.b64 {%0,%1},%2;" : "=r"(lo[c]), "=r"(hi[c]) : "l"(acc[p][c]));
        int r_lo = row0 + rbase + 2 * p;
        if (r_lo < N) {
            float4 v = make_float4(__uint_as_float(lo[0]), __uint_as_float(lo[1]),
                                   __uint_as_float(lo[2]), __uint_as_float(lo[3]));
            *(float4*)(out + (size_t)r_lo * 64 + tx * 4) = v;
        }
        int r_hi = r_lo + 1;
        if (r_hi < N) {
            float4 v = make_float4(__uint_as_float(hi[0]), __uint_as_float(hi[1]),
                                   __uint_as_float(hi[2]), __uint_as_float(hi[3]));
            *(float4*)(out + (size_t)r_hi * 64 + tx * 4) = v;
        }
    }
}

// ============================================================================
extern "C" void kernel_launch(void* const* d_in, const int* in_sizes, int n_in,
                              void* d_out, int out_size) {
    const float* x  = (const float*)d_in[0];           // [N, 64]
    const int*   ei = (const int*)d_in[1];             // [2, E]
    const float* ew = (const float*)d_in[2];           // [E]
    const float* tf = (const float*)d_in[3];           // [3, 64, 64]
    const float* tb = (const float*)d_in[4];           // [3, 64, 64]
    float* out = (float*)d_out;

    const int N = in_sizes[0] / C;                     // 50000
    const int E = in_sizes[2];                         // 800000
    const int* row = ei;
    const int* col = ei + E;

    // 1. degree + histogram (cnt/deg/total are zero at call entry:
    //    static init on call 1, scatter's tail on later calls)
    deg_hist_kernel<<<(E + 255) / 256, 256>>>(row, ew, E);

    // 2. unordered CSR segment assignment + dinv (replaces 3-kernel scan)
    assign_kernel<<<(N + 511) / 512, 512>>>(N);

    // 3. packed CSR scatter (norm fused) + state re-zero for next call
    scatter_kernel<<<(E + 255) / 256, 256>>>(row, col, ew, E, N);

    // 4. three diffusion steps (gather, no atomics): one warp per node
    int prop_blocks = (N + 7) / 8;
    prop_csr_kernel<<<prop_blocks, 256>>>(x, 0, N);
    prop_csr_kernel<<<prop_blocks, 256>>>(x, 1, N);
    prop_csr_kernel<<<prop_blocks, 256>>>(x, 2, N);

    // 5. fused 4-way GEMM epilogue (theta fold in staging, fp32x2 FMA)
    out_gemm_kernel<<<(N + BM - 1) / BM, 256>>>(x, tf, tb, out, N);
}

// round 10
// speedup vs baseline: 1.1160x; 1.0551x over previous
#include <cuda_runtime.h>
#include <cuda_fp16.h>
#include <cuda_bf16.h>
#include <cstdint>

// Problem constants (DiffusionConv: N=50000, E=800000, C=64, K=3)
#define NMAX 50000
#define EMAX 800000
#define C    64

// -------- device scratch (no allocs; statically zero-initialized) --------
__device__ __align__(16) __half g_xh[NMAX * C];    // fp16 gather sources
__device__ __align__(16) __half g_T1h[NMAX * C];
__device__ __align__(16) __half g_T2h[NMAX * C];
__device__ float g_T3[NMAX * C];                   // fp32 (GEMM input only)
__device__ float g_dinv[NMAX];
__device__ unsigned long long g_dc[NMAX];  // packed: cnt<<40 | Q8.24 weighted deg
__device__ int   g_rowbeg[NMAX];
__device__ int   g_rowend[NMAX];
__device__ int   g_cur[NMAX];
__device__ int   g_total;                  // segment-claim cursor
__device__ unsigned long long g_epack[EMAX];   // (norm<<32)|col

// ---------------- packed fp32x2 helpers ----------------
#define FMA2(d, a, b) \
    asm("fma.rn.f32x2 %0, %1, %2, %3;" : "=l"(d) : "l"(a), "l"(b), "l"(d))

// ---------------- degree+count (single packed atomic) + x->fp16 -------------
// Q8.24 fixed point for weighted degree: w in [0,1), deg < 64 -> fits 40 bits.
__global__ void deg_hist_kernel(const int* __restrict__ row,
                                const float* __restrict__ w,
                                const float* __restrict__ x, int E, int N) {
    int e = blockIdx.x * blockDim.x + threadIdx.x;
    if (e < E) {
        int r = row[e];
        unsigned long long q =
            (unsigned long long)(w[e] * 16777216.0f + 0.5f);   // Q.24
        atomicAdd(&g_dc[r], (1ULL << 40) | q);
    }
    // ride-along: convert x -> fp16 (N*8 = 400000 < E threads)
    if (e < N * 8) {
        int rrow = e >> 3, ch = (e & 7) << 3;    // 8 channels per thread
        const float4* p = (const float4*)(x + (size_t)rrow * C + ch);
        float4 a = p[0], b = p[1];
        __half2 h0 = __floats2half2_rn(a.x, a.y);
        __half2 h1 = __floats2half2_rn(a.z, a.w);
        __half2 h2 = __floats2half2_rn(b.x, b.y);
        __half2 h3 = __floats2half2_rn(b.z, b.w);
        uint4 u;
        u.x = *(unsigned*)&h0; u.y = *(unsigned*)&h1;
        u.z = *(unsigned*)&h2; u.w = *(unsigned*)&h3;
        *(uint4*)(g_xh + (size_t)rrow * C + ch) = u;
    }
}

// ---------------- assign: unordered CSR segment claim + dinv ----------------
__global__ void assign_kernel(int N) {
    __shared__ int wsum[16];
    __shared__ int gbase;
    int tid = threadIdx.x;
    int i = blockIdx.x * 512 + tid;
    int lane = tid & 31, wid = tid >> 5;

    unsigned long long dc = (i < N) ? g_dc[i] : 0ULL;
    int v = (int)(dc >> 40);
    int s = v;
#pragma unroll
    for (int off = 1; off < 32; off <<= 1) {
        int t = __shfl_up_sync(0xffffffffu, s, off);
        if (lane >= off) s += t;
    }
    if (lane == 31) wsum[wid] = s;
    __syncthreads();
    if (wid == 0) {
        int ws = (lane < 16) ? wsum[lane] : 0;
#pragma unroll
        for (int off = 1; off < 16; off <<= 1) {
            int t = __shfl_up_sync(0xffffffffu, ws, off);
            if (lane >= off) ws += t;
        }
        if (lane < 16) wsum[lane] = ws;
    }
    __syncthreads();
    if (tid == 0) gbase = atomicAdd(&g_total, wsum[15]);
    __syncthreads();
    if (i < N) {
        int base = gbase + ((wid > 0) ? wsum[wid - 1] : 0);
        int beg = base + s - v;
        g_rowbeg[i] = beg;
        g_rowend[i] = beg + v;
        g_cur[i] = beg;
        float d = (float)(double)(dc & ((1ULL << 40) - 1)) * (1.0f / 16777216.0f);
        g_dinv[i] = (d > 0.f) ? rsqrtf(d) : 0.f;
    }
}

// ---------------- scatter edges into packed CSR (norm fused) ----------------
// Tail: re-zero g_dc/g_total for the next call (call 1 covered by static init).
__global__ void scatter_kernel(const int* __restrict__ row,
                               const int* __restrict__ col,
                               const float* __restrict__ w, int E, int N) {
    int e = blockIdx.x * blockDim.x + threadIdx.x;
    if (e < E) {
        int r = row[e], c = col[e];
        float nm = g_dinv[r] * w[e] * g_dinv[c];
        int pos = atomicAdd(&g_cur[r], 1);
        unsigned long long p =
            ((unsigned long long)__float_as_uint(nm) << 32) | (unsigned)c;
        g_epack[pos] = p;
    }
    if (e < N) g_dc[e] = 0ULL;
    if (e == 0) g_total = 0;
}

// ---------------- propagate via CSR gather: one warp per node ---------------
// fp16 gather (128B/row = 1 L1 wavefront/edge), fp32 accumulate, no atomics.
// Steps 0,1 write fp16 only (next gather + GEMM converts in staging);
// step 2 writes fp32 only (GEMM input). Scratch selected device-side.
__global__ void prop_csr_kernel(int step, int N) {
    const __half2* __restrict__ src = (const __half2*)
        ((step == 0) ? g_xh : (step == 1 ? g_T1h : g_T2h));

    int warp = (int)((blockIdx.x * blockDim.x + threadIdx.x) >> 5);
    if (warp >= N) return;
    int lane = threadIdx.x & 31;

    int beg = g_rowbeg[warp];
    int end = g_rowend[warp];

    float ax = 0.f, ay = 0.f;
    int e = beg;
    for (; e + 8 <= end; e += 8) {
        unsigned long long pk[8];
#pragma unroll
        for (int j = 0; j < 8; j++) pk[j] = g_epack[e + j];
        float2 v[8];
#pragma unroll
        for (int j = 0; j < 8; j++) {
            int c = (int)(unsigned)pk[j];
            v[j] = __half22float2(src[(c << 5) + lane]);
        }
#pragma unroll
        for (int j = 0; j < 8; j++) {
            float nm = __uint_as_float((unsigned)(pk[j] >> 32));
            ax = fmaf(nm, v[j].x, ax);
            ay = fmaf(nm, v[j].y, ay);
        }
    }
    for (; e < end; e++) {
        unsigned long long p = g_epack[e];
        int c = (int)(unsigned)p;
        float nm = __uint_as_float((unsigned)(p >> 32));
        float2 vv = __half22float2(src[(c << 5) + lane]);
        ax = fmaf(nm, vv.x, ax);
        ay = fmaf(nm, vv.y, ay);
    }
    if (step == 0)
        *(__half2*)(g_T1h + ((size_t)warp << 6) + (lane << 1)) =
            __floats2half2_rn(ax, ay);
    else if (step == 1)
        *(__half2*)(g_T2h + ((size_t)warp << 6) + (lane << 1)) =
            __floats2half2_rn(ax, ay);
    else
        *(float2*)(g_T3 + ((size_t)warp << 6) + (lane << 1)) =
            make_float2(ax, ay);
}

// ---------------- fused epilogue GEMM: out = sum_s A_s @ W_s ----------------
// A0 = x (fp32), A1 = T1h (fp16->fp32 in staging), A2 = T2h, A3 = T3 (fp32).
// W fold in staging: W0=Tf0, W1=Tb0+Tb1, W2=Tf1+Tb2, W3=Tf2.
// BM=128 rows/block, 256 threads, thread tile 8 rows x 4 cols, packed fp32x2.
#define BM 128
__global__ void out_gemm_kernel(const float* __restrict__ x,
                                const float* __restrict__ tf,
                                const float* __restrict__ tb,
                                float* __restrict__ out, int N) {
    __shared__ float sW[64 * 64];        // 16 KB
    __shared__ float sA[32 * 130];       // 16.25 KB, k-major

    int t = threadIdx.x;
    int tx = t & 15;
    int ty = t >> 4;
    int row0 = blockIdx.x * BM;
    int rbase = ty * 8;

    unsigned long long acc[4][4];
#pragma unroll
    for (int p = 0; p < 4; p++)
#pragma unroll
        for (int c = 0; c < 4; c++) acc[p][c] = 0ull;

#pragma unroll
    for (int s = 0; s < 4; s++) {
        __syncthreads();
        {   // stage W_s with theta fold
            const float4* tf4 = (const float4*)tf;
            const float4* tb4 = (const float4*)tb;
            float4* Ws4 = (float4*)sW;
            for (int i = t; i < 1024; i += 256) {
                float4 v;
                if (s == 0) v = tf4[i];
                else if (s == 1) {
                    float4 a = tb4[i], b = tb4[1024 + i];
                    v = make_float4(a.x + b.x, a.y + b.y, a.z + b.z, a.w + b.w);
                } else if (s == 2) {
                    float4 a = tf4[1024 + i], b = tb4[2048 + i];
                    v = make_float4(a.x + b.x, a.y + b.y, a.z + b.z, a.w + b.w);
                } else v = tf4[2048 + i];
                Ws4[i] = v;
            }
        }

        for (int kh = 0; kh < 2; kh++) {
            __syncthreads();
#pragma unroll
            for (int it = 0; it < 4; it++) {
                int idx = it * 256 + t;
                int r = idx >> 3;
                int kc = (idx & 7) << 2;
                float4 v = make_float4(0.f, 0.f, 0.f, 0.f);
                int gr = row0 + r;
                if (gr < N) {
                    if (s == 0)
                        v = *(const float4*)(x + (size_t)gr * 64 + kh * 32 + kc);
                    else if (s == 3)
                        v = *(const float4*)(g_T3 + (size_t)gr * 64 + kh * 32 + kc);
                    else {
                        const __half* Ah = (s == 1) ? g_T1h : g_T2h;
                        uint2 u = *(const uint2*)(Ah + (size_t)gr * 64 + kh * 32 + kc);
                        float2 f0 = __half22float2(*(__half2*)&u.x);
                        float2 f1 = __half22float2(*(__half2*)&u.y);
                        v = make_float4(f0.x, f0.y, f1.x, f1.y);
                    }
                }
                sA[(kc + 0) * 130 + r] = v.x;
                sA[(kc + 1) * 130 + r] = v.y;
                sA[(kc + 2) * 130 + r] = v.z;
                sA[(kc + 3) * 130 + r] = v.w;
            }
            __syncthreads();
#pragma unroll
            for (int k4 = 0; k4 < 8; k4++) {
#pragma unroll
                for (int kk = 0; kk < 4; kk++) {
                    int kl = k4 * 4 + kk;
                    float4 w4 = *(const float4*)&sW[(kh * 32 + kl) * 64 + tx * 4];
                    unsigned long long wp0, wp1, wp2, wp3;
                    unsigned int u0 = __float_as_uint(w4.x);
                    unsigned int u1 = __float_as_uint(w4.y);
                    unsigned int u2 = __float_as_uint(w4.z);
                    unsigned int u3 = __float_as_uint(w4.w);
                    asm("mov.b64 %0,{%1,%1};" : "=l"(wp0) : "r"(u0));
                    asm("mov.b64 %0,{%1,%1};" : "=l"(wp1) : "r"(u1));
                    asm("mov.b64 %0,{%1,%1};" : "=l"(wp2) : "r"(u2));
                    asm("mov.b64 %0,{%1,%1};" : "=l"(wp3) : "r"(u3));
                    const unsigned long long* ap =
                        (const unsigned long long*)&sA[kl * 130 + rbase];
                    unsigned long long a0 = ap[0], a1 = ap[1];
                    unsigned long long a2 = ap[2], a3 = ap[3];
                    FMA2(acc[0][0], a0, wp0); FMA2(acc[0][1], a0, wp1);
                    FMA2(acc[0][2], a0, wp2); FMA2(acc[0][3], a0, wp3);
                    FMA2(acc[1][0], a1, wp0); FMA2(acc[1][1], a1, wp1);
                    FMA2(acc[1][2], a1, wp2); FMA2(acc[1][3], a1, wp3);
                    FMA2(acc[2][0], a2, wp0); FMA2(acc[2][1], a2, wp1);
                    FMA2(acc[2][2], a2, wp2); FMA2(acc[2][3], a2, wp3);
                    FMA2(acc[3][0], a3, wp0); FMA2(acc[3][1], a3, wp1);
                    FMA2(acc[3][2], a3, wp2); FMA2(acc[3][3], a3, wp3);
                }
            }
        }
    }

#pragma unroll
    for (int p = 0; p < 4; p++) {
        unsigned int lo[4], hi[4];
#pragma unroll
        for (int c = 0; c < 4; c++)
            asm("mov.b64 {%0,%1},%2;" : "=r"(lo[c]), "=r"(hi[c]) : "l"(acc[p][c]));
        int r_lo = row0 + rbase + 2 * p;
        if (r_lo < N) {
            float4 v = make_float4(__uint_as_float(lo[0]), __uint_as_float(lo[1]),
                                   __uint_as_float(lo[2]), __uint_as_float(lo[3]));
            *(float4*)(out + (size_t)r_lo * 64 + tx * 4) = v;
        }
        int r_hi = r_lo + 1;
        if (r_hi < N) {
            float4 v = make_float4(__uint_as_float(hi[0]), __uint_as_float(hi[1]),
                                   __uint_as_float(hi[2]), __uint_as_float(hi[3]));
            *(float4*)(out + (size_t)r_hi * 64 + tx * 4) = v;
        }
    }
}

// ============================================================================
extern "C" void kernel_launch(void* const* d_in, const int* in_sizes, int n_in,
                              void* d_out, int out_size) {
    const float* x  = (const float*)d_in[0];           // [N, 64]
    const int*   ei = (const int*)d_in[1];             // [2, E]
    const float* ew = (const float*)d_in[2];           // [E]
    const float* tf = (const float*)d_in[3];           // [3, 64, 64]
    const float* tb = (const float*)d_in[4];           // [3, 64, 64]
    float* out = (float*)d_out;

    const int N = in_sizes[0] / C;                     // 50000
    const int E = in_sizes[2];                         // 800000
    const int* row = ei;
    const int* col = ei + E;

    // 1. packed degree+count atomic, x->fp16 ride-along
    deg_hist_kernel<<<(E + 255) / 256, 256>>>(row, ew, x, E, N);

    // 2. unordered CSR segment assignment + dinv
    assign_kernel<<<(N + 511) / 512, 512>>>(N);

    // 3. packed CSR scatter (norm fused) + state re-zero for next call
    scatter_kernel<<<(E + 255) / 256, 256>>>(row, col, ew, E, N);

    // 4. three diffusion steps (fp16 gather, fp32 accumulate)
    int prop_blocks = (N + 7) / 8;
    prop_csr_kernel<<<prop_blocks, 256>>>(0, N);
    prop_csr_kernel<<<prop_blocks, 256>>>(1, N);
    prop_csr_kernel<<<prop_blocks, 256>>>(2, N);

    // 5. fused 4-way GEMM epilogue (theta fold + fp16 convert in staging)
    out_gemm_kernel<<<(N + BM - 1) / BM, 256>>>(x, tf, tb, out, N);
}

// round 11
// speedup vs baseline: 1.1584x; 1.0380x over previous
#include <cuda_runtime.h>
#include <cuda_fp16.h>
#include <cuda_bf16.h>
#include <cstdint>

// Problem constants (DiffusionConv: N=50000, E=800000, C=64, K=3)
#define NMAX 50000
#define EMAX 800000
#define C    64

// -------- device scratch (no allocs; statically zero-initialized) --------
__device__ __align__(16) __half g_xh[NMAX * C];    // fp16 gather sources
__device__ __align__(16) __half g_T1h[NMAX * C];
__device__ __align__(16) __half g_T2h[NMAX * C];
__device__ float g_T3[NMAX * C];                   // fp32 (GEMM input only)
__device__ float g_dinv[NMAX];
__device__ unsigned long long g_dc[NMAX];  // packed: cnt<<40 | Q8.24 weighted deg
__device__ int   g_rowbeg[NMAX];
__device__ int   g_rowend[NMAX];
__device__ int   g_cur[NMAX];
__device__ int   g_total;                  // segment-claim cursor
__device__ unsigned long long g_epack[EMAX];   // (norm<<32)|col

// ---------------- packed fp32x2 helpers ----------------
#define FMA2(d, a, b) \
    asm("fma.rn.f32x2 %0, %1, %2, %3;" : "=l"(d) : "l"(a), "l"(b), "l"(d))

// ---------------- degree+count (single packed atomic) + x->fp16 -------------
// Q8.24 fixed point for weighted degree: w in [0,1), deg < 64 -> fits 40 bits.
__global__ void deg_hist_kernel(const int* __restrict__ row,
                                const float* __restrict__ w,
                                const float* __restrict__ x, int E, int N) {
    int e = blockIdx.x * blockDim.x + threadIdx.x;
    if (e < E) {
        int r = row[e];
        unsigned long long q =
            (unsigned long long)(w[e] * 16777216.0f + 0.5f);   // Q.24
        atomicAdd(&g_dc[r], (1ULL << 40) | q);
    }
    // ride-along: convert x -> fp16 (N*8 = 400000 < E threads)
    if (e < N * 8) {
        int rrow = e >> 3, ch = (e & 7) << 3;    // 8 channels per thread
        const float4* p = (const float4*)(x + (size_t)rrow * C + ch);
        float4 a = p[0], b = p[1];
        __half2 h0 = __floats2half2_rn(a.x, a.y);
        __half2 h1 = __floats2half2_rn(a.z, a.w);
        __half2 h2 = __floats2half2_rn(b.x, b.y);
        __half2 h3 = __floats2half2_rn(b.z, b.w);
        uint4 u;
        u.x = *(unsigned*)&h0; u.y = *(unsigned*)&h1;
        u.z = *(unsigned*)&h2; u.w = *(unsigned*)&h3;
        *(uint4*)(g_xh + (size_t)rrow * C + ch) = u;
    }
}

// ---------------- assign: unordered CSR segment claim + dinv ----------------
__global__ void assign_kernel(int N) {
    __shared__ int wsum[16];
    __shared__ int gbase;
    int tid = threadIdx.x;
    int i = blockIdx.x * 512 + tid;
    int lane = tid & 31, wid = tid >> 5;

    unsigned long long dc = (i < N) ? g_dc[i] : 0ULL;
    int v = (int)(dc >> 40);
    int s = v;
#pragma unroll
    for (int off = 1; off < 32; off <<= 1) {
        int t = __shfl_up_sync(0xffffffffu, s, off);
        if (lane >= off) s += t;
    }
    if (lane == 31) wsum[wid] = s;
    __syncthreads();
    if (wid == 0) {
        int ws = (lane < 16) ? wsum[lane] : 0;
#pragma unroll
        for (int off = 1; off < 16; off <<= 1) {
            int t = __shfl_up_sync(0xffffffffu, ws, off);
            if (lane >= off) ws += t;
        }
        if (lane < 16) wsum[lane] = ws;
    }
    __syncthreads();
    if (tid == 0) gbase = atomicAdd(&g_total, wsum[15]);
    __syncthreads();
    if (i < N) {
        int base = gbase + ((wid > 0) ? wsum[wid - 1] : 0);
        int beg = base + s - v;
        g_rowbeg[i] = beg;
        g_rowend[i] = beg + v;
        g_cur[i] = beg;
        float d = (float)(double)(dc & ((1ULL << 40) - 1)) * (1.0f / 16777216.0f);
        g_dinv[i] = (d > 0.f) ? rsqrtf(d) : 0.f;
    }
}

// ---------------- scatter edges into packed CSR (norm fused) ----------------
// Tail: re-zero g_dc/g_total for the next call (call 1 covered by static init).
__global__ void scatter_kernel(const int* __restrict__ row,
                               const int* __restrict__ col,
                               const float* __restrict__ w, int E, int N) {
    int e = blockIdx.x * blockDim.x + threadIdx.x;
    if (e < E) {
        int r = row[e], c = col[e];
        float nm = g_dinv[r] * w[e] * g_dinv[c];
        int pos = atomicAdd(&g_cur[r], 1);
        unsigned long long p =
            ((unsigned long long)__float_as_uint(nm) << 32) | (unsigned)c;
        g_epack[pos] = p;
    }
    if (e < N) g_dc[e] = 0ULL;
    if (e == 0) g_total = 0;
}

// ---------------- propagate via CSR gather: one warp per node ---------------
// NEW layout: 16 lanes x 2 edges in parallel. Lane l covers channels
// (l&15)*4..+3 of edge-half (l>>4). Gather = one 8B uint2 (4 halves) per
// lane per edge -> half the load instructions, 2x edge MLP vs R10.
// fp32 accumulate; cross-half shfl_xor(16) reduce; lanes 0-15 store.
// Steps 0,1 write fp16 (next gather source); step 2 writes fp32 (GEMM).
__global__ void prop_csr_kernel(int step, int N) {
    const __half* __restrict__ src =
        (step == 0) ? g_xh : (step == 1 ? g_T1h : g_T2h);

    int warp = (int)((blockIdx.x * blockDim.x + threadIdx.x) >> 5);
    if (warp >= N) return;
    int lane = threadIdx.x & 31;
    int half = lane >> 4;                  // which edge of the pair
    int ch4  = (lane & 15) << 2;           // 4-channel base

    int beg = g_rowbeg[warp];
    int end = g_rowend[warp];

    float a0 = 0.f, a1 = 0.f, a2 = 0.f, a3 = 0.f;
    int e = beg;

    // main: 4 pairs = 8 edges per iteration
    for (; e + 8 <= end; e += 8) {
        unsigned long long pk[4];
#pragma unroll
        for (int j = 0; j < 4; j++) pk[j] = g_epack[e + 2 * j + half];
        uint2 v[4];
#pragma unroll
        for (int j = 0; j < 4; j++) {
            int c = (int)(unsigned)pk[j];
            v[j] = *(const uint2*)(src + ((size_t)c << 6) + ch4);
        }
#pragma unroll
        for (int j = 0; j < 4; j++) {
            float nm = __uint_as_float((unsigned)(pk[j] >> 32));
            float2 f0 = __half22float2(*(__half2*)&v[j].x);
            float2 f1 = __half22float2(*(__half2*)&v[j].y);
            a0 = fmaf(nm, f0.x, a0); a1 = fmaf(nm, f0.y, a1);
            a2 = fmaf(nm, f1.x, a2); a3 = fmaf(nm, f1.y, a3);
        }
    }
    // pair tail
    for (; e + 2 <= end; e += 2) {
        unsigned long long p = g_epack[e + half];
        int c = (int)(unsigned)p;
        float nm = __uint_as_float((unsigned)(p >> 32));
        uint2 v = *(const uint2*)(src + ((size_t)c << 6) + ch4);
        float2 f0 = __half22float2(*(__half2*)&v.x);
        float2 f1 = __half22float2(*(__half2*)&v.y);
        a0 = fmaf(nm, f0.x, a0); a1 = fmaf(nm, f0.y, a1);
        a2 = fmaf(nm, f1.x, a2); a3 = fmaf(nm, f1.y, a3);
    }
    // single leftover edge: half 1 contributes 0
    if (e < end) {
        unsigned long long p = g_epack[e];
        int c = (int)(unsigned)p;
        float nm = half ? 0.f : __uint_as_float((unsigned)(p >> 32));
        uint2 v = *(const uint2*)(src + ((size_t)c << 6) + ch4);
        float2 f0 = __half22float2(*(__half2*)&v.x);
        float2 f1 = __half22float2(*(__half2*)&v.y);
        a0 = fmaf(nm, f0.x, a0); a1 = fmaf(nm, f0.y, a1);
        a2 = fmaf(nm, f1.x, a2); a3 = fmaf(nm, f1.y, a3);
    }

    // combine the two edge-halves
    a0 += __shfl_xor_sync(0xffffffffu, a0, 16);
    a1 += __shfl_xor_sync(0xffffffffu, a1, 16);
    a2 += __shfl_xor_sync(0xffffffffu, a2, 16);
    a3 += __shfl_xor_sync(0xffffffffu, a3, 16);

    if (lane < 16) {
        if (step == 2) {
            *(float4*)(g_T3 + ((size_t)warp << 6) + ch4) =
                make_float4(a0, a1, a2, a3);
        } else {
            __half* dsth = (step == 0) ? g_T1h : g_T2h;
            __half2 h0 = __floats2half2_rn(a0, a1);
            __half2 h1 = __floats2half2_rn(a2, a3);
            uint2 u;
            u.x = *(unsigned*)&h0; u.y = *(unsigned*)&h1;
            *(uint2*)(dsth + ((size_t)warp << 6) + ch4) = u;
        }
    }
}

// ---------------- fused epilogue GEMM: out = sum_s A_s @ W_s ----------------
// A0 = x (fp32), A1 = T1h (fp16->fp32 in staging), A2 = T2h, A3 = T3 (fp32).
// W fold in staging: W0=Tf0, W1=Tb0+Tb1, W2=Tf1+Tb2, W3=Tf2.
// BM=128 rows/block, 256 threads, thread tile 8 rows x 4 cols, packed fp32x2.
#define BM 128
__global__ void out_gemm_kernel(const float* __restrict__ x,
                                const float* __restrict__ tf,
                                const float* __restrict__ tb,
                                float* __restrict__ out, int N) {
    __shared__ float sW[64 * 64];        // 16 KB
    __shared__ float sA[32 * 130];       // 16.25 KB, k-major

    int t = threadIdx.x;
    int tx = t & 15;
    int ty = t >> 4;
    int row0 = blockIdx.x * BM;
    int rbase = ty * 8;

    unsigned long long acc[4][4];
#pragma unroll
    for (int p = 0; p < 4; p++)
#pragma unroll
        for (int c = 0; c < 4; c++) acc[p][c] = 0ull;

#pragma unroll
    for (int s = 0; s < 4; s++) {
        __syncthreads();
        {   // stage W_s with theta fold
            const float4* tf4 = (const float4*)tf;
            const float4* tb4 = (const float4*)tb;
            float4* Ws4 = (float4*)sW;
            for (int i = t; i < 1024; i += 256) {
                float4 v;
                if (s == 0) v = tf4[i];
                else if (s == 1) {
                    float4 a = tb4[i], b = tb4[1024 + i];
                    v = make_float4(a.x + b.x, a.y + b.y, a.z + b.z, a.w + b.w);
                } else if (s == 2) {
                    float4 a = tf4[1024 + i], b = tb4[2048 + i];
                    v = make_float4(a.x + b.x, a.y + b.y, a.z + b.z, a.w + b.w);
                } else v = tf4[2048 + i];
                Ws4[i] = v;
            }
        }

        for (int kh = 0; kh < 2; kh++) {
            __syncthreads();
#pragma unroll
            for (int it = 0; it < 4; it++) {
                int idx = it * 256 + t;
                int r = idx >> 3;
                int kc = (idx & 7) << 2;
                float4 v = make_float4(0.f, 0.f, 0.f, 0.f);
                int gr = row0 + r;
                if (gr < N) {
                    if (s == 0)
                        v = *(const float4*)(x + (size_t)gr * 64 + kh * 32 + kc);
                    else if (s == 3)
                        v = *(const float4*)(g_T3 + (size_t)gr * 64 + kh * 32 + kc);
                    else {
                        const __half* Ah = (s == 1) ? g_T1h : g_T2h;
                        uint2 u = *(const uint2*)(Ah + (size_t)gr * 64 + kh * 32 + kc);
                        float2 f0 = __half22float2(*(__half2*)&u.x);
                        float2 f1 = __half22float2(*(__half2*)&u.y);
                        v = make_float4(f0.x, f0.y, f1.x, f1.y);
                    }
                }
                sA[(kc + 0) * 130 + r] = v.x;
                sA[(kc + 1) * 130 + r] = v.y;
                sA[(kc + 2) * 130 + r] = v.z;
                sA[(kc + 3) * 130 + r] = v.w;
            }
            __syncthreads();
#pragma unroll
            for (int k4 = 0; k4 < 8; k4++) {
#pragma unroll
                for (int kk = 0; kk < 4; kk++) {
                    int kl = k4 * 4 + kk;
                    float4 w4 = *(const float4*)&sW[(kh * 32 + kl) * 64 + tx * 4];
                    unsigned long long wp0, wp1, wp2, wp3;
                    unsigned int u0 = __float_as_uint(w4.x);
                    unsigned int u1 = __float_as_uint(w4.y);
                    unsigned int u2 = __float_as_uint(w4.z);
                    unsigned int u3 = __float_as_uint(w4.w);
                    asm("mov.b64 %0,{%1,%1};" : "=l"(wp0) : "r"(u0));
                    asm("mov.b64 %0,{%1,%1};" : "=l"(wp1) : "r"(u1));
                    asm("mov.b64 %0,{%1,%1};" : "=l"(wp2) : "r"(u2));
                    asm("mov.b64 %0,{%1,%1};" : "=l"(wp3) : "r"(u3));
                    const unsigned long long* ap =
                        (const unsigned long long*)&sA[kl * 130 + rbase];
                    unsigned long long a0 = ap[0], a1 = ap[1];
                    unsigned long long a2 = ap[2], a3 = ap[3];
                    FMA2(acc[0][0], a0, wp0); FMA2(acc[0][1], a0, wp1);
                    FMA2(acc[0][2], a0, wp2); FMA2(acc[0][3], a0, wp3);
                    FMA2(acc[1][0], a1, wp0); FMA2(acc[1][1], a1, wp1);
                    FMA2(acc[1][2], a1, wp2); FMA2(acc[1][3], a1, wp3);
                    FMA2(acc[2][0], a2, wp0); FMA2(acc[2][1], a2, wp1);
                    FMA2(acc[2][2], a2, wp2); FMA2(acc[2][3], a2, wp3);
                    FMA2(acc[3][0], a3, wp0); FMA2(acc[3][1], a3, wp1);
                    FMA2(acc[3][2], a3, wp2); FMA2(acc[3][3], a3, wp3);
                }
            }
        }
    }

#pragma unroll
    for (int p = 0; p < 4; p++) {
        unsigned int lo[4], hi[4];
#pragma unroll
        for (int c = 0; c < 4; c++)
            asm("mov.b64 {%0,%1},%2;" : "=r"(lo[c]), "=r"(hi[c]) : "l"(acc[p][c]));
        int r_lo = row0 + rbase + 2 * p;
        if (r_lo < N) {
            float4 v = make_float4(__uint_as_float(lo[0]), __uint_as_float(lo[1]),
                                   __uint_as_float(lo[2]), __uint_as_float(lo[3]));
            *(float4*)(out + (size_t)r_lo * 64 + tx * 4) = v;
        }
        int r_hi = r_lo + 1;
        if (r_hi < N) {
            float4 v = make_float4(__uint_as_float(hi[0]), __uint_as_float(hi[1]),
                                   __uint_as_float(hi[2]), __uint_as_float(hi[3]));
            *(float4*)(out + (size_t)r_hi * 64 + tx * 4) = v;
        }
    }
}

// ============================================================================
extern "C" void kernel_launch(void* const* d_in, const int* in_sizes, int n_in,
                              void* d_out, int out_size) {
    const float* x  = (const float*)d_in[0];           // [N, 64]
    const int*   ei = (const int*)d_in[1];             // [2, E]
    const float* ew = (const float*)d_in[2];           // [E]
    const float* tf = (const float*)d_in[3];           // [3, 64, 64]
    const float* tb = (const float*)d_in[4];           // [3, 64, 64]
    float* out = (float*)d_out;

    const int N = in_sizes[0] / C;                     // 50000
    const int E = in_sizes[2];                         // 800000
    const int* row = ei;
    const int* col = ei + E;

    // 1. packed degree+count atomic, x->fp16 ride-along
    deg_hist_kernel<<<(E + 255) / 256, 256>>>(row, ew, x, E, N);

    // 2. unordered CSR segment assignment + dinv
    assign_kernel<<<(N + 511) / 512, 512>>>(N);

    // 3. packed CSR scatter (norm fused) + state re-zero for next call
    scatter_kernel<<<(E + 255) / 256, 256>>>(row, col, ew, E, N);

    // 4. three diffusion steps (fp16 gather, 2-edge-parallel warps)
    int prop_blocks = (N + 7) / 8;
    prop_csr_kernel<<<prop_blocks, 256>>>(0, N);
    prop_csr_kernel<<<prop_blocks, 256>>>(1, N);
    prop_csr_kernel<<<prop_blocks, 256>>>(2, N);

    // 5. fused 4-way GEMM epilogue (theta fold + fp16 convert in staging)
    out_gemm_kernel<<<(N + BM - 1) / BM, 256>>>(x, tf, tb, out, N);
}

// round 13
// speedup vs baseline: 1.3181x; 1.1379x over previous
#include <cuda_runtime.h>
#include <cuda_fp16.h>
#include <cuda_bf16.h>
#include <cstdint>

// Problem constants (DiffusionConv: N=50000, E=800000, C=64, K=3)
#define NMAX 50000
#define EMAX 800000
#define C    64

// -------- device scratch (no allocs; statically zero-initialized) --------
__device__ __align__(16) __half g_xh[NMAX * C];    // fp16 gather sources
__device__ __align__(16) __half g_T1h[NMAX * C];
__device__ __align__(16) __half g_T2h[NMAX * C];
__device__ float g_T3[NMAX * C];                   // fp32 (GEMM input only)
__device__ float g_dinv[NMAX];
__device__ unsigned long long g_dc[NMAX];  // packed: cnt<<40 | Q8.24 weighted deg
__device__ int   g_rowbeg[NMAX];
__device__ int   g_rowend[NMAX];
__device__ int   g_cur[NMAX];
__device__ int   g_total;                  // segment-claim cursor
__device__ unsigned long long g_epack[EMAX];   // (norm<<32)|col

// ---------------- degree+count (single packed atomic) + x->fp16 -------------
__global__ void deg_hist_kernel(const int* __restrict__ row,
                                const float* __restrict__ w,
                                const float* __restrict__ x, int E, int N) {
    int e = blockIdx.x * blockDim.x + threadIdx.x;
    if (e < E) {
        int r = row[e];
        unsigned long long q =
            (unsigned long long)(w[e] * 16777216.0f + 0.5f);   // Q.24
        atomicAdd(&g_dc[r], (1ULL << 40) | q);
    }
    if (e < N * 8) {
        int rrow = e >> 3, ch = (e & 7) << 3;
        const float4* p = (const float4*)(x + (size_t)rrow * C + ch);
        float4 a = p[0], b = p[1];
        __half2 h0 = __floats2half2_rn(a.x, a.y);
        __half2 h1 = __floats2half2_rn(a.z, a.w);
        __half2 h2 = __floats2half2_rn(b.x, b.y);
        __half2 h3 = __floats2half2_rn(b.z, b.w);
        uint4 u;
        u.x = *(unsigned*)&h0; u.y = *(unsigned*)&h1;
        u.z = *(unsigned*)&h2; u.w = *(unsigned*)&h3;
        *(uint4*)(g_xh + (size_t)rrow * C + ch) = u;
    }
}

// ---------------- assign: unordered CSR segment claim + dinv ----------------
__global__ void assign_kernel(int N) {
    __shared__ int wsum[16];
    __shared__ int gbase;
    int tid = threadIdx.x;
    int i = blockIdx.x * 512 + tid;
    int lane = tid & 31, wid = tid >> 5;

    unsigned long long dc = (i < N) ? g_dc[i] : 0ULL;
    int v = (int)(dc >> 40);
    int s = v;
#pragma unroll
    for (int off = 1; off < 32; off <<= 1) {
        int t = __shfl_up_sync(0xffffffffu, s, off);
        if (lane >= off) s += t;
    }
    if (lane == 31) wsum[wid] = s;
    __syncthreads();
    if (wid == 0) {
        int ws = (lane < 16) ? wsum[lane] : 0;
#pragma unroll
        for (int off = 1; off < 16; off <<= 1) {
            int t = __shfl_up_sync(0xffffffffu, ws, off);
            if (lane >= off) ws += t;
        }
        if (lane < 16) wsum[lane] = ws;
    }
    __syncthreads();
    if (tid == 0) gbase = atomicAdd(&g_total, wsum[15]);
    __syncthreads();
    if (i < N) {
        int base = gbase + ((wid > 0) ? wsum[wid - 1] : 0);
        int beg = base + s - v;
        g_rowbeg[i] = beg;
        g_rowend[i] = beg + v;
        g_cur[i] = beg;
        float d = (float)(double)(dc & ((1ULL << 40) - 1)) * (1.0f / 16777216.0f);
        g_dinv[i] = (d > 0.f) ? rsqrtf(d) : 0.f;
    }
}

// ---------------- scatter edges into packed CSR (norm fused) ----------------
__global__ void scatter_kernel(const int* __restrict__ row,
                               const int* __restrict__ col,
                               const float* __restrict__ w, int E, int N) {
    int e = blockIdx.x * blockDim.x + threadIdx.x;
    if (e < E) {
        int r = row[e], c = col[e];
        float nm = g_dinv[r] * w[e] * g_dinv[c];
        int pos = atomicAdd(&g_cur[r], 1);
        unsigned long long p =
            ((unsigned long long)__float_as_uint(nm) << 32) | (unsigned)c;
        g_epack[pos] = p;
    }
    if (e < N) g_dc[e] = 0ULL;
    if (e == 0) g_total = 0;
}

// ---------------- propagate via CSR gather: one warp per node ---------------
// 16 lanes x 2 edges in parallel (unchanged from R11 — at its practical floor).
__global__ void prop_csr_kernel(int step, int N) {
    const __half* __restrict__ src =
        (step == 0) ? g_xh : (step == 1 ? g_T1h : g_T2h);

    int warp = (int)((blockIdx.x * blockDim.x + threadIdx.x) >> 5);
    if (warp >= N) return;
    int lane = threadIdx.x & 31;
    int half = lane >> 4;
    int ch4  = (lane & 15) << 2;

    int beg = g_rowbeg[warp];
    int end = g_rowend[warp];

    float a0 = 0.f, a1 = 0.f, a2 = 0.f, a3 = 0.f;
    int e = beg;

    for (; e + 8 <= end; e += 8) {
        unsigned long long pk[4];
#pragma unroll
        for (int j = 0; j < 4; j++) pk[j] = g_epack[e + 2 * j + half];
        uint2 v[4];
#pragma unroll
        for (int j = 0; j < 4; j++) {
            int c = (int)(unsigned)pk[j];
            v[j] = *(const uint2*)(src + ((size_t)c << 6) + ch4);
        }
#pragma unroll
        for (int j = 0; j < 4; j++) {
            float nm = __uint_as_float((unsigned)(pk[j] >> 32));
            float2 f0 = __half22float2(*(__half2*)&v[j].x);
            float2 f1 = __half22float2(*(__half2*)&v[j].y);
            a0 = fmaf(nm, f0.x, a0); a1 = fmaf(nm, f0.y, a1);
            a2 = fmaf(nm, f1.x, a2); a3 = fmaf(nm, f1.y, a3);
        }
    }
    for (; e + 2 <= end; e += 2) {
        unsigned long long p = g_epack[e + half];
        int c = (int)(unsigned)p;
        float nm = __uint_as_float((unsigned)(p >> 32));
        uint2 v = *(const uint2*)(src + ((size_t)c << 6) + ch4);
        float2 f0 = __half22float2(*(__half2*)&v.x);
        float2 f1 = __half22float2(*(__half2*)&v.y);
        a0 = fmaf(nm, f0.x, a0); a1 = fmaf(nm, f0.y, a1);
        a2 = fmaf(nm, f1.x, a2); a3 = fmaf(nm, f1.y, a3);
    }
    if (e < end) {
        unsigned long long p = g_epack[e];
        int c = (int)(unsigned)p;
        float nm = half ? 0.f : __uint_as_float((unsigned)(p >> 32));
        uint2 v = *(const uint2*)(src + ((size_t)c << 6) + ch4);
        float2 f0 = __half22float2(*(__half2*)&v.x);
        float2 f1 = __half22float2(*(__half2*)&v.y);
        a0 = fmaf(nm, f0.x, a0); a1 = fmaf(nm, f0.y, a1);
        a2 = fmaf(nm, f1.x, a2); a3 = fmaf(nm, f1.y, a3);
    }

    a0 += __shfl_xor_sync(0xffffffffu, a0, 16);
    a1 += __shfl_xor_sync(0xffffffffu, a1, 16);
    a2 += __shfl_xor_sync(0xffffffffu, a2, 16);
    a3 += __shfl_xor_sync(0xffffffffu, a3, 16);

    if (lane < 16) {
        if (step == 2) {
            *(float4*)(g_T3 + ((size_t)warp << 6) + ch4) =
                make_float4(a0, a1, a2, a3);
        } else {
            __half* dsth = (step == 0) ? g_T1h : g_T2h;
            __half2 h0 = __floats2half2_rn(a0, a1);
            __half2 h1 = __floats2half2_rn(a2, a3);
            uint2 u;
            u.x = *(unsigned*)&h0; u.y = *(unsigned*)&h1;
            *(uint2*)(dsth + ((size_t)warp << 6) + ch4) = u;
        }
    }
}

// ---------------- tf32 tensor-core epilogue: out = sum_s A_s @ W_s ----------
// 256 threads = 8 warps; block tile 128 rows x 64 cols; warp tile 16 x 64.
// mma.sync m16n8k8 tf32, fp32 accumulate. A fragments loaded straight from
// global (no A smem). W folded + tf32-converted + FRAGMENT-PERMUTED into a
// 16KB smem buffer so each B fragment is one conflict-free LDS.64.
// W fold: W0=Tf0, W1=Tb0+Tb1, W2=Tf1+Tb2, W3=Tf2.
__device__ __forceinline__ unsigned f2tf32(float f) {
    unsigned u;
    asm("cvt.rna.tf32.f32 %0, %1;" : "=r"(u) : "f"(f));
    return u;
}

__global__ void out_gemm_kernel(const float* __restrict__ x,
                                const float* __restrict__ tf,
                                const float* __restrict__ tb,
                                float* __restrict__ out, int N) {
    // sWp[(chunk*8 + ntile)*32 + lane] = { W[k0+tig][n], W[k0+4+tig][n] }
    // where k0 = chunk*8, tig = lane&3, n = ntile*8 + (lane>>2).
    __shared__ float2 sWp[2048];          // 16 KB

    int t = threadIdx.x;
    int lane = t & 31;
    int w = t >> 5;
    int gid = lane >> 2;                  // group id (row within fragment)
    int tig = lane & 3;                   // thread in group (k within fragment)
    int row0 = blockIdx.x * 128 + w * 16;

    float c[8][4];
#pragma unroll
    for (int n = 0; n < 8; n++)
#pragma unroll
        for (int j = 0; j < 4; j++) c[n][j] = 0.f;

#pragma unroll
    for (int s = 0; s < 4; s++) {
        __syncthreads();   // prior src done reading sWp
        // ---- stage folded, tf32-rounded, fragment-permuted W ----
        for (int i = t; i < 2048; i += 256) {
            int chunk = i >> 8;
            int ntile = (i >> 5) & 7;
            int ln = i & 31;
            int k = chunk * 8 + (ln & 3);
            int n = ntile * 8 + (ln >> 2);
            float b0, b1;
            int i0 = k * 64 + n, i1 = (k + 4) * 64 + n;
            if (s == 0)      { b0 = tf[i0];              b1 = tf[i1]; }
            else if (s == 1) { b0 = tb[i0] + tb[4096 + i0];
                               b1 = tb[i1] + tb[4096 + i1]; }
            else if (s == 2) { b0 = tf[4096 + i0] + tb[8192 + i0];
                               b1 = tf[4096 + i1] + tb[8192 + i1]; }
            else             { b0 = tf[8192 + i0];       b1 = tf[8192 + i1]; }
            float2 p;
            p.x = __uint_as_float(f2tf32(b0));
            p.y = __uint_as_float(f2tf32(b1));
            sWp[i] = p;
        }
        __syncthreads();

        int r0 = row0 + gid;
        int r1 = r0 + 8;
        bool v0 = r0 < N, v1 = r1 < N;

#pragma unroll
        for (int chunk = 0; chunk < 8; chunk++) {
            int k = chunk * 8 + tig;
            unsigned a0, a1, a2, a3;
            if (s == 0) {
                a0 = v0 ? f2tf32(x[(size_t)r0 * 64 + k]) : 0u;
                a1 = v1 ? f2tf32(x[(size_t)r1 * 64 + k]) : 0u;
                a2 = v0 ? f2tf32(x[(size_t)r0 * 64 + k + 4]) : 0u;
                a3 = v1 ? f2tf32(x[(size_t)r1 * 64 + k + 4]) : 0u;
            } else if (s == 3) {
                a0 = v0 ? f2tf32(g_T3[(size_t)r0 * 64 + k]) : 0u;
                a1 = v1 ? f2tf32(g_T3[(size_t)r1 * 64 + k]) : 0u;
                a2 = v0 ? f2tf32(g_T3[(size_t)r0 * 64 + k + 4]) : 0u;
                a3 = v1 ? f2tf32(g_T3[(size_t)r1 * 64 + k + 4]) : 0u;
            } else {
                const __half* Ah = (s == 1) ? g_T1h : g_T2h;
                a0 = v0 ? f2tf32(__half2float(Ah[(size_t)r0 * 64 + k])) : 0u;
                a1 = v1 ? f2tf32(__half2float(Ah[(size_t)r1 * 64 + k])) : 0u;
                a2 = v0 ? f2tf32(__half2float(Ah[(size_t)r0 * 64 + k + 4])) : 0u;
                a3 = v1 ? f2tf32(__half2float(Ah[(size_t)r1 * 64 + k + 4])) : 0u;
            }
#pragma unroll
            for (int ntile = 0; ntile < 8; ntile++) {
                float2 b = sWp[(chunk * 8 + ntile) * 32 + lane];
                unsigned b0 = __float_as_uint(b.x);
                unsigned b1 = __float_as_uint(b.y);
                asm("mma.sync.aligned.m16n8k8.row.col.f32.tf32.tf32.f32 "
                    "{%0,%1,%2,%3}, {%4,%5,%6,%7}, {%8,%9}, {%0,%1,%2,%3};"
                    : "+f"(c[ntile][0]), "+f"(c[ntile][1]),
                      "+f"(c[ntile][2]), "+f"(c[ntile][3])
                    : "r"(a0), "r"(a1), "r"(a2), "r"(a3), "r"(b0), "r"(b1));
            }
        }
    }

    // writeout: c0,c1 -> (row0+gid, ntile*8+2*tig+{0,1}); c2,c3 -> row+8
    int r0 = row0 + gid;
    int r1 = r0 + 8;
#pragma unroll
    for (int ntile = 0; ntile < 8; ntile++) {
        int colb = ntile * 8 + 2 * tig;
        if (r0 < N)
            *(float2*)(out + (size_t)r0 * 64 + colb) =
                make_float2(c[ntile][0], c[ntile][1]);
        if (r1 < N)
            *(float2*)(out + (size_t)r1 * 64 + colb) =
                make_float2(c[ntile][2], c[ntile][3]);
    }
}

// ============================================================================
extern "C" void kernel_launch(void* const* d_in, const int* in_sizes, int n_in,
                              void* d_out, int out_size) {
    const float* x  = (const float*)d_in[0];           // [N, 64]
    const int*   ei = (const int*)d_in[1];             // [2, E]
    const float* ew = (const float*)d_in[2];           // [E]
    const float* tf = (const float*)d_in[3];           // [3, 64, 64]
    const float* tb = (const float*)d_in[4];           // [3, 64, 64]
    float* out = (float*)d_out;

    const int N = in_sizes[0] / C;                     // 50000
    const int E = in_sizes[2];                         // 800000
    const int* row = ei;
    const int* col = ei + E;

    // 1. packed degree+count atomic, x->fp16 ride-along
    deg_hist_kernel<<<(E + 255) / 256, 256>>>(row, ew, x, E, N);

    // 2. unordered CSR segment assignment + dinv
    assign_kernel<<<(N + 511) / 512, 512>>>(N);

    // 3. packed CSR scatter (norm fused) + state re-zero for next call
    scatter_kernel<<<(E + 255) / 256, 256>>>(row, col, ew, E, N);

    // 4. three diffusion steps (fp16 gather, 2-edge-parallel warps)
    int prop_blocks = (N + 7) / 8;
    prop_csr_kernel<<<prop_blocks, 256>>>(0, N);
    prop_csr_kernel<<<prop_blocks, 256>>>(1, N);
    prop_csr_kernel<<<prop_blocks, 256>>>(2, N);

    // 5. tf32 tensor-core epilogue (theta fold + permute in staging)
    out_gemm_kernel<<<(N + 127) / 128, 256>>>(x, tf, tb, out, N);
}